// round 2
// baseline (speedup 1.0000x reference)
#include <cuda_runtime.h>
#include <math.h>

#define BB 8
#define CC 256
#define NN 4096
#define DD 32

// ---------------- scratch (device globals; no allocation) ----------------
__device__ float g_q[BB * NN * DD];   // [b][n][d]
__device__ float g_k[BB * NN * DD];   // [b][n][d]
__device__ float g_v[BB * CC * NN];   // [b][c][n]
__device__ float g_ms[BB * 2 * CC];   // [b][mean(256) | std(256)]
__device__ float g_a[BB * CC];        // sigmoid gate

// =====================================================================
// Kernel 1: fused QKV projection.
// Out[r][n] = W[r]·x[:,n] + bias[r], rows 0..31 = q, 32..63 = k, 64..319 = v
// Tile: 64 rows x 128 cols, k-chunks of 32. Microtile 4r x 8n per thread.
// =====================================================================
__global__ __launch_bounds__(256) void proj_kernel(
    const float* __restrict__ x,
    const float* __restrict__ Wq, const float* __restrict__ bq,
    const float* __restrict__ Wk, const float* __restrict__ bk,
    const float* __restrict__ Wv, const float* __restrict__ bv)
{
    __shared__ float Ws[32][68];    // [c][r] transposed, padded
    __shared__ float Xs[32][128];   // [c][n]

    const int b  = blockIdx.z;
    const int r0 = blockIdx.y * 64;
    const int n0 = blockIdx.x * 128;
    const int t  = threadIdx.x;
    const int rg = t >> 4;          // 0..15  (rows rg*4..rg*4+3)
    const int ng = t & 15;          // 0..15  (cols ng*4..+3 and 64+ng*4..+3)

    float acc[4][8];
#pragma unroll
    for (int i = 0; i < 4; i++)
#pragma unroll
        for (int j = 0; j < 8; j++) acc[i][j] = 0.f;

    for (int c0 = 0; c0 < 256; c0 += 32) {
        // load X tile: 32 rows x 128 cols
        for (int i = t; i < 1024; i += 256) {
            int row = i >> 5, c4 = i & 31;
            *(float4*)&Xs[row][c4 * 4] =
                *(const float4*)&x[((size_t)(b * 256 + c0 + row)) * 4096 + n0 + c4 * 4];
        }
        // load W tile transposed: Ws[c][r]
        for (int i = t; i < 2048; i += 256) {
            int r = i >> 5, c = i & 31;
            int rr = r0 + r;
            float w;
            if (rr < 32)       w = Wq[rr * 256 + c0 + c];
            else if (rr < 64)  w = Wk[(rr - 32) * 256 + c0 + c];
            else               w = Wv[(rr - 64) * 256 + c0 + c];
            Ws[c][r] = w;
        }
        __syncthreads();
#pragma unroll
        for (int c = 0; c < 32; c++) {
            float4 w4 = *(const float4*)&Ws[c][rg * 4];
            float4 xa = *(const float4*)&Xs[c][ng * 4];
            float4 xb = *(const float4*)&Xs[c][64 + ng * 4];
            float wv[4] = {w4.x, w4.y, w4.z, w4.w};
            float xv[8] = {xa.x, xa.y, xa.z, xa.w, xb.x, xb.y, xb.z, xb.w};
#pragma unroll
            for (int i = 0; i < 4; i++)
#pragma unroll
                for (int j = 0; j < 8; j++)
                    acc[i][j] = fmaf(wv[i], xv[j], acc[i][j]);
        }
        __syncthreads();
    }

    // bias
    float bias[4];
#pragma unroll
    for (int i = 0; i < 4; i++) {
        int rr = r0 + rg * 4 + i;
        if (rr < 32)       bias[i] = bq[rr];
        else if (rr < 64)  bias[i] = bk[rr - 32];
        else               bias[i] = bv[rr - 64];
    }
#pragma unroll
    for (int i = 0; i < 4; i++)
#pragma unroll
        for (int j = 0; j < 8; j++) acc[i][j] += bias[i];

    // store
    if (r0 == 0) {
        // q rows (rg<8) or k rows (rg>=8): layout [b][n][32], transpose in regs
        float* dst = (rg < 8) ? g_q : g_k;
        int dbase = (rg < 8) ? rg * 4 : (rg - 8) * 4;
#pragma unroll
        for (int j = 0; j < 8; j++) {
            int n = n0 + ((j < 4) ? (ng * 4 + j) : (64 + ng * 4 + (j - 4)));
            float4 v4 = make_float4(acc[0][j], acc[1][j], acc[2][j], acc[3][j]);
            *(float4*)&dst[((size_t)(b * 4096 + n)) * 32 + dbase] = v4;
        }
    } else {
        int cbase = r0 + rg * 4 - 64;
#pragma unroll
        for (int i = 0; i < 4; i++) {
            float4 va = make_float4(acc[i][0], acc[i][1], acc[i][2], acc[i][3]);
            float4 vb = make_float4(acc[i][4], acc[i][5], acc[i][6], acc[i][7]);
            size_t base = ((size_t)(b * 256 + cbase + i)) * 4096 + n0;
            *(float4*)&g_v[base + ng * 4]      = va;
            *(float4*)&g_v[base + 64 + ng * 4] = vb;
        }
    }
}

// =====================================================================
// Kernel 2: per-(b,c) mean + unbiased std over N=4096
// =====================================================================
__global__ __launch_bounds__(256) void se_reduce(const float* __restrict__ x)
{
    __shared__ float rs[8], rq[8];
    const int row = blockIdx.x;                  // b*256 + c
    const float4* xp = (const float4*)(x + (size_t)row * 4096);
    const int t = threadIdx.x;
    float s = 0.f, q = 0.f;
    for (int i = t; i < 1024; i += 256) {
        float4 v = xp[i];
        s += (v.x + v.y) + (v.z + v.w);
        q += v.x * v.x + v.y * v.y + v.z * v.z + v.w * v.w;
    }
#pragma unroll
    for (int o = 16; o; o >>= 1) {
        s += __shfl_down_sync(0xffffffffu, s, o);
        q += __shfl_down_sync(0xffffffffu, q, o);
    }
    if ((t & 31) == 0) { rs[t >> 5] = s; rq[t >> 5] = q; }
    __syncthreads();
    if (t == 0) {
        float S = 0.f, Q = 0.f;
#pragma unroll
        for (int w = 0; w < 8; w++) { S += rs[w]; Q += rq[w]; }
        float mean = S * (1.f / 4096.f);
        float var  = (Q - S * S * (1.f / 4096.f)) * (1.f / 4095.f);
        int b = row >> 8, c = row & 255;
        g_ms[b * 512 + c]       = mean;
        g_ms[b * 512 + 256 + c] = sqrtf(fmaxf(var, 0.f));
    }
}

// =====================================================================
// Kernel 3: per-batch MLP: a = sigmoid(relu(inp @ W1^T) @ W2^T)
// =====================================================================
__global__ __launch_bounds__(256) void se_mlp(
    const float* __restrict__ W1, const float* __restrict__ W2)
{
    __shared__ float inp[512], hid[32];
    const int b = blockIdx.x;
    const int t = threadIdx.x;
    inp[t]       = g_ms[b * 512 + t];
    inp[t + 256] = g_ms[b * 512 + 256 + t];
    __syncthreads();
    // hidden: 32 rows, 8 lanes per row
    int r = t >> 3, l8 = t & 7;
    float s = 0.f;
    for (int j = l8; j < 512; j += 8) s = fmaf(W1[r * 512 + j], inp[j], s);
    s += __shfl_down_sync(0xffffffffu, s, 4, 8);
    s += __shfl_down_sync(0xffffffffu, s, 2, 8);
    s += __shfl_down_sync(0xffffffffu, s, 1, 8);
    if (l8 == 0) hid[r] = fmaxf(s, 0.f);
    __syncthreads();
    float a = 0.f;
#pragma unroll
    for (int rr = 0; rr < 32; rr++) a = fmaf(W2[t * 32 + rr], hid[rr], a);
    g_a[b * 256 + t] = 1.f / (1.f + __expf(-a));
}

// =====================================================================
// Kernel 4: fused flash attention. Per block: batch b, 64-query tile.
// Writes out = gamma * sp.
// smem (floats): qs[64*36] ks[64*36] M[64] l[64] f[64] psum[256]
//                ps[64*68] vs[64*256]; epilogue reuses ps..vs as [256][65]
// =====================================================================
#define SM_QS   0
#define SM_KS   2304
#define SM_M    4608
#define SM_L    4672
#define SM_F    4736
#define SM_PSUM 4800
#define SM_PS   5056
#define SM_VS   9408
#define SM_TOT  25792   // floats -> 103168 bytes

__global__ __launch_bounds__(256, 2) void attn_kernel(
    float* __restrict__ out, const float* __restrict__ gamma_p)
{
    extern __shared__ float sm[];
    float* qs   = sm + SM_QS;    // [m][36]
    float* ks   = sm + SM_KS;    // [n][36]
    float* Mrow = sm + SM_M;
    float* lrow = sm + SM_L;
    float* fsm  = sm + SM_F;
    float* psum = sm + SM_PSUM;
    float* ps   = sm + SM_PS;    // [n][68] (cols = m)
    float* vs   = sm + SM_VS;    // [n][256]

    const int b  = blockIdx.y;
    const int m0 = blockIdx.x * 64;
    const int t  = threadIdx.x;
    const int tm = t >> 5;   // warp id: rows tm*8..+7
    const int tc = t & 31;   // channel lane: c = tc + 32*j
    const int mg = t >> 4;   // score phase: rows mg*4..+3
    const int sg = t & 15;   // score phase: cols sg + 16*j

    // load Q tile once
    for (int i = t; i < 512; i += 256) {
        int mm = i >> 3, d4 = (i & 7) * 4;
        *(float4*)&qs[mm * 36 + d4] =
            *(const float4*)&g_q[((size_t)(b * 4096 + m0 + mm)) * 32 + d4];
    }
    if (t < 64) { Mrow[t] = -INFINITY; lrow[t] = 0.f; }

    float acc[8][8];
#pragma unroll
    for (int i = 0; i < 8; i++)
#pragma unroll
        for (int j = 0; j < 8; j++) acc[i][j] = 0.f;

    for (int kt = 0; kt < 64; kt++) {
        const int n0 = kt * 64;
        __syncthreads();   // protect ks/vs/ps from previous iteration readers

        // load K tile
        for (int i = t; i < 512; i += 256) {
            int nn = i >> 3, d4 = (i & 7) * 4;
            *(float4*)&ks[nn * 36 + d4] =
                *(const float4*)&g_k[((size_t)(b * 4096 + n0 + nn)) * 32 + d4];
        }
        // load V tile transposed: vs[n][c], thread owns channel c = t
        {
            const float* vp = &g_v[((size_t)(b * 256 + t)) * 4096 + n0];
#pragma unroll
            for (int j4 = 0; j4 < 16; j4++) {
                float4 v = *(const float4*)&vp[j4 * 4];
                vs[(j4 * 4 + 0) * 256 + t] = v.x;
                vs[(j4 * 4 + 1) * 256 + t] = v.y;
                vs[(j4 * 4 + 2) * 256 + t] = v.z;
                vs[(j4 * 4 + 3) * 256 + t] = v.w;
            }
        }
        __syncthreads();

        // scores: s[mg*4+i][sg+16*j]
        {
            float s4[4][4];
#pragma unroll
            for (int i = 0; i < 4; i++)
#pragma unroll
                for (int j = 0; j < 4; j++) s4[i][j] = 0.f;
#pragma unroll
            for (int d = 0; d < 32; d += 4) {
                float4 q4[4], k4[4];
#pragma unroll
                for (int i = 0; i < 4; i++)
                    q4[i] = *(const float4*)&qs[(mg * 4 + i) * 36 + d];
#pragma unroll
                for (int j = 0; j < 4; j++)
                    k4[j] = *(const float4*)&ks[(sg + 16 * j) * 36 + d];
#pragma unroll
                for (int i = 0; i < 4; i++)
#pragma unroll
                    for (int j = 0; j < 4; j++)
                        s4[i][j] += q4[i].x * k4[j].x + q4[i].y * k4[j].y
                                  + q4[i].z * k4[j].z + q4[i].w * k4[j].w;
            }
#pragma unroll
            for (int j = 0; j < 4; j++)
#pragma unroll
                for (int i = 0; i < 4; i++)
                    ps[(sg + 16 * j) * 68 + mg * 4 + i] = s4[i][j];
        }
        __syncthreads();

        // row max + rescale factor
        if (t < 64) {
            float mx = -INFINITY;
#pragma unroll 8
            for (int n = 0; n < 64; n++) mx = fmaxf(mx, ps[n * 68 + t]);
            float oldM = Mrow[t];
            float newM = fmaxf(oldM, mx);
            fsm[t] = __expf(oldM - newM);
            Mrow[t] = newM;
        }
        __syncthreads();

        // exp + partial row sums (all 256 threads)
        {
            int m = t & 63, nc = t >> 6;
            float Mm = Mrow[m];
            float s = 0.f;
#pragma unroll
            for (int n = nc * 16; n < nc * 16 + 16; n++) {
                float p = __expf(ps[n * 68 + m] - Mm);
                ps[n * 68 + m] = p;
                s += p;
            }
            psum[t] = s;
        }
        __syncthreads();

        if (t < 64)
            lrow[t] = lrow[t] * fsm[t]
                    + psum[t] + psum[t + 64] + psum[t + 128] + psum[t + 192];

        // rescale accumulators
        {
            float fr[8];
#pragma unroll
            for (int i = 0; i < 8; i++) fr[i] = fsm[tm * 8 + i];
#pragma unroll
            for (int i = 0; i < 8; i++)
#pragma unroll
                for (int j = 0; j < 8; j++) acc[i][j] *= fr[i];
        }

        // PV accumulate: acc[m][c] += p[m][n] * v[n][c]
#pragma unroll 2
        for (int n = 0; n < 64; n++) {
            float4 pa = *(const float4*)&ps[n * 68 + tm * 8];
            float4 pb = *(const float4*)&ps[n * 68 + tm * 8 + 4];
            float vv[8];
#pragma unroll
            for (int j = 0; j < 8; j++) vv[j] = vs[n * 256 + tc + 32 * j];
#pragma unroll
            for (int j = 0; j < 8; j++) {
                acc[0][j] = fmaf(pa.x, vv[j], acc[0][j]);
                acc[1][j] = fmaf(pa.y, vv[j], acc[1][j]);
                acc[2][j] = fmaf(pa.z, vv[j], acc[2][j]);
                acc[3][j] = fmaf(pa.w, vv[j], acc[3][j]);
                acc[4][j] = fmaf(pb.x, vv[j], acc[4][j]);
                acc[5][j] = fmaf(pb.y, vv[j], acc[5][j]);
                acc[6][j] = fmaf(pb.z, vv[j], acc[6][j]);
                acc[7][j] = fmaf(pb.w, vv[j], acc[7][j]);
            }
        }
    }
    __syncthreads();

    // epilogue: scale by gamma/l, transpose through smem, coalesced store
    const float g = gamma_p[0];
    float scl[8];
#pragma unroll
    for (int i = 0; i < 8; i++) scl[i] = g / lrow[tm * 8 + i];

    float* smt = ps;  // reuse ps..vs region: [256][65]
#pragma unroll
    for (int i = 0; i < 8; i++)
#pragma unroll
        for (int j = 0; j < 8; j++)
            smt[(tc + 32 * j) * 65 + tm * 8 + i] = acc[i][j] * scl[i];
    __syncthreads();

    for (int idx = t; idx < 64 * 256; idx += 256) {
        int c = idx >> 6, m = idx & 63;
        out[((size_t)(b * 256 + c)) * 4096 + m0 + m] = smt[c * 65 + m];
    }
}

// =====================================================================
// Kernel 5: out += (1 + lamb * a[b,c]) * x
// =====================================================================
__global__ __launch_bounds__(256) void final_kernel(
    float* __restrict__ out, const float* __restrict__ x,
    const float* __restrict__ lamb)
{
    const int i4  = blockIdx.x * 256 + threadIdx.x;  // float4 index, < 2097152
    const int row = i4 >> 10;                        // b*256 + c
    const float fac = 1.f + lamb[0] * g_a[row];
    float4 xv = ((const float4*)x)[i4];
    float4 ov = ((float4*)out)[i4];
    ov.x = fmaf(fac, xv.x, ov.x);
    ov.y = fmaf(fac, xv.y, ov.y);
    ov.z = fmaf(fac, xv.z, ov.z);
    ov.w = fmaf(fac, xv.w, ov.w);
    ((float4*)out)[i4] = ov;
}

// =====================================================================
extern "C" void kernel_launch(void* const* d_in, const int* in_sizes, int n_in,
                              void* d_out, int out_size)
{
    const float* x     = (const float*)d_in[0];
    const float* Wq    = (const float*)d_in[1];
    const float* bq    = (const float*)d_in[2];
    const float* Wk    = (const float*)d_in[3];
    const float* bk    = (const float*)d_in[4];
    const float* Wv    = (const float*)d_in[5];
    const float* bv    = (const float*)d_in[6];
    const float* gamma = (const float*)d_in[7];
    const float* W1    = (const float*)d_in[8];
    const float* W2    = (const float*)d_in[9];
    const float* lamb  = (const float*)d_in[10];
    float* out = (float*)d_out;

    cudaFuncSetAttribute(attn_kernel,
                         cudaFuncAttributeMaxDynamicSharedMemorySize,
                         SM_TOT * (int)sizeof(float));

    proj_kernel<<<dim3(32, 5, 8), 256>>>(x, Wq, bq, Wk, bk, Wv, bv);
    se_reduce<<<2048, 256>>>(x);
    se_mlp<<<8, 256>>>(W1, W2);
    attn_kernel<<<dim3(64, 8), 256, SM_TOT * sizeof(float)>>>(out, gamma);
    final_kernel<<<8192, 256>>>(out, x, lamb);
}

// round 7
// speedup vs baseline: 2.0140x; 2.0140x over previous
#include <cuda_runtime.h>
#include <math.h>

#define BB 8
#define CC 256
#define NN 4096
#define DD 32

// ---------------- scratch (device globals; no allocation) ----------------
__device__ float g_q[BB * NN * DD];   // [b][n][d]
__device__ float g_k[BB * NN * DD];   // [b][n][d]
__device__ float g_v[BB * CC * NN];   // [b][c][n]
__device__ float g_ms[BB * 2 * CC];   // [b][mean(256) | std(256)]
__device__ float g_a[BB * CC];        // sigmoid gate

// ---------------- tf32 helpers ----------------
__device__ __forceinline__ unsigned f2tf_u(float f) {
    unsigned u;
    asm("cvt.rna.tf32.f32 %0, %1;" : "=r"(u) : "f"(f));
    return u;
}
__device__ __forceinline__ float f2tf_f(float f) {
    return __uint_as_float(f2tf_u(f));
}
__device__ __forceinline__ void mma_tf32(float* d, const unsigned* a,
                                         const unsigned* b) {
    asm volatile(
        "mma.sync.aligned.m16n8k8.row.col.f32.tf32.tf32.f32 "
        "{%0,%1,%2,%3}, {%4,%5,%6,%7}, {%8,%9}, {%0,%1,%2,%3};"
        : "+f"(d[0]), "+f"(d[1]), "+f"(d[2]), "+f"(d[3])
        : "r"(a[0]), "r"(a[1]), "r"(a[2]), "r"(a[3]), "r"(b[0]), "r"(b[1]));
}

// =====================================================================
// Kernel 1: fused QKV projection.
// =====================================================================
__global__ __launch_bounds__(256) void proj_kernel(
    const float* __restrict__ x,
    const float* __restrict__ Wq, const float* __restrict__ bq,
    const float* __restrict__ Wk, const float* __restrict__ bk,
    const float* __restrict__ Wv, const float* __restrict__ bv)
{
    __shared__ float Ws[32][68];
    __shared__ float Xs[32][128];

    const int b  = blockIdx.z;
    const int r0 = blockIdx.y * 64;
    const int n0 = blockIdx.x * 128;
    const int t  = threadIdx.x;
    const int rg = t >> 4;
    const int ng = t & 15;

    float acc[4][8];
#pragma unroll
    for (int i = 0; i < 4; i++)
#pragma unroll
        for (int j = 0; j < 8; j++) acc[i][j] = 0.f;

    for (int c0 = 0; c0 < 256; c0 += 32) {
        for (int i = t; i < 1024; i += 256) {
            int row = i >> 5, c4 = i & 31;
            *(float4*)&Xs[row][c4 * 4] =
                *(const float4*)&x[((size_t)(b * 256 + c0 + row)) * 4096 + n0 + c4 * 4];
        }
        for (int i = t; i < 2048; i += 256) {
            int r = i >> 5, c = i & 31;
            int rr = r0 + r;
            float w;
            if (rr < 32)       w = Wq[rr * 256 + c0 + c];
            else if (rr < 64)  w = Wk[(rr - 32) * 256 + c0 + c];
            else               w = Wv[(rr - 64) * 256 + c0 + c];
            Ws[c][r] = w;
        }
        __syncthreads();
#pragma unroll
        for (int c = 0; c < 32; c++) {
            float4 w4 = *(const float4*)&Ws[c][rg * 4];
            float4 xa = *(const float4*)&Xs[c][ng * 4];
            float4 xb = *(const float4*)&Xs[c][64 + ng * 4];
            float wv[4] = {w4.x, w4.y, w4.z, w4.w};
            float xv[8] = {xa.x, xa.y, xa.z, xa.w, xb.x, xb.y, xb.z, xb.w};
#pragma unroll
            for (int i = 0; i < 4; i++)
#pragma unroll
                for (int j = 0; j < 8; j++)
                    acc[i][j] = fmaf(wv[i], xv[j], acc[i][j]);
        }
        __syncthreads();
    }

    float bias[4];
#pragma unroll
    for (int i = 0; i < 4; i++) {
        int rr = r0 + rg * 4 + i;
        if (rr < 32)       bias[i] = bq[rr];
        else if (rr < 64)  bias[i] = bk[rr - 32];
        else               bias[i] = bv[rr - 64];
    }
#pragma unroll
    for (int i = 0; i < 4; i++)
#pragma unroll
        for (int j = 0; j < 8; j++) acc[i][j] += bias[i];

    if (r0 == 0) {
        float* dst = (rg < 8) ? g_q : g_k;
        int dbase = (rg < 8) ? rg * 4 : (rg - 8) * 4;
#pragma unroll
        for (int j = 0; j < 8; j++) {
            int n = n0 + ((j < 4) ? (ng * 4 + j) : (64 + ng * 4 + (j - 4)));
            float4 v4 = make_float4(acc[0][j], acc[1][j], acc[2][j], acc[3][j]);
            *(float4*)&dst[((size_t)(b * 4096 + n)) * 32 + dbase] = v4;
        }
    } else {
        int cbase = r0 + rg * 4 - 64;
#pragma unroll
        for (int i = 0; i < 4; i++) {
            float4 va = make_float4(acc[i][0], acc[i][1], acc[i][2], acc[i][3]);
            float4 vb = make_float4(acc[i][4], acc[i][5], acc[i][6], acc[i][7]);
            size_t base = ((size_t)(b * 256 + cbase + i)) * 4096 + n0;
            *(float4*)&g_v[base + ng * 4]      = va;
            *(float4*)&g_v[base + 64 + ng * 4] = vb;
        }
    }
}

// =====================================================================
// Kernel 2: per-(b,c) mean + unbiased std
// =====================================================================
__global__ __launch_bounds__(256) void se_reduce(const float* __restrict__ x)
{
    __shared__ float rs[8], rq[8];
    const int row = blockIdx.x;
    const float4* xp = (const float4*)(x + (size_t)row * 4096);
    const int t = threadIdx.x;
    float s = 0.f, q = 0.f;
    for (int i = t; i < 1024; i += 256) {
        float4 v = xp[i];
        s += (v.x + v.y) + (v.z + v.w);
        q += v.x * v.x + v.y * v.y + v.z * v.z + v.w * v.w;
    }
#pragma unroll
    for (int o = 16; o; o >>= 1) {
        s += __shfl_down_sync(0xffffffffu, s, o);
        q += __shfl_down_sync(0xffffffffu, q, o);
    }
    if ((t & 31) == 0) { rs[t >> 5] = s; rq[t >> 5] = q; }
    __syncthreads();
    if (t == 0) {
        float S = 0.f, Q = 0.f;
#pragma unroll
        for (int w = 0; w < 8; w++) { S += rs[w]; Q += rq[w]; }
        float mean = S * (1.f / 4096.f);
        float var  = (Q - S * S * (1.f / 4096.f)) * (1.f / 4095.f);
        int b = row >> 8, c = row & 255;
        g_ms[b * 512 + c]       = mean;
        g_ms[b * 512 + 256 + c] = sqrtf(fmaxf(var, 0.f));
    }
}

// =====================================================================
// Kernel 3: per-batch SE MLP
// =====================================================================
__global__ __launch_bounds__(256) void se_mlp(
    const float* __restrict__ W1, const float* __restrict__ W2)
{
    __shared__ float inp[512], hid[32];
    const int b = blockIdx.x;
    const int t = threadIdx.x;
    inp[t]       = g_ms[b * 512 + t];
    inp[t + 256] = g_ms[b * 512 + 256 + t];
    __syncthreads();
    int r = t >> 3, l8 = t & 7;
    float s = 0.f;
    for (int j = l8; j < 512; j += 8) s = fmaf(W1[r * 512 + j], inp[j], s);
    s += __shfl_down_sync(0xffffffffu, s, 4, 8);
    s += __shfl_down_sync(0xffffffffu, s, 2, 8);
    s += __shfl_down_sync(0xffffffffu, s, 1, 8);
    if (l8 == 0) hid[r] = fmaxf(s, 0.f);
    __syncthreads();
    float a = 0.f;
#pragma unroll
    for (int rr = 0; rr < 32; rr++) a = fmaf(W2[t * 32 + rr], hid[rr], a);
    g_a[b * 256 + t] = 1.f / (1.f + __expf(-a));
}

// =====================================================================
// Kernel 4: flash attention with tf32 mma.sync (m16n8k8).
// Per CTA: batch b, 64-query tile. 8 warps.
//   QK layout: wr = warp>>1 (m16 group), wc = warp&1 (n32 group)
//   PV layout: wrp = warp>>2 (m32 group), wcp = warp&3 (c64 group)
// smem strides chosen for conflict-free fragment LDS:
//   qs/ks stride 36, ps stride 68, vs stride 264 (== 8 mod 32)
// =====================================================================
#define SM_QS   0          // 64*36   = 2304
#define SM_KS   2304       // 64*36   = 2304
#define SM_PS   4608       // 64*68   = 4352   (epilogue smt: 256*68 from here)
#define SM_VS   8960       // 64*264  = 16896
#define SM_M    25856      // 64
#define SM_L    25920      // 64
#define SM_F    25984      // 64
#define SM_PSUM 26048      // 128
#define SM_WMAX 26176      // 128
#define SM_TOT  26304      // floats -> 105216 bytes

__global__ __launch_bounds__(256, 2) void attn_kernel(
    float* __restrict__ out, const float* __restrict__ gamma_p)
{
    extern __shared__ float sm[];
    float* qs   = sm + SM_QS;
    float* ks   = sm + SM_KS;
    float* ps   = sm + SM_PS;
    float* vs   = sm + SM_VS;
    float* Mrow = sm + SM_M;
    float* lrow = sm + SM_L;
    float* fsm  = sm + SM_F;
    float* psum = sm + SM_PSUM;
    float* wmax = sm + SM_WMAX;

    const int b    = blockIdx.y;
    const int m0   = blockIdx.x * 64;
    const int t    = threadIdx.x;
    const int warp = t >> 5;
    const int lane = t & 31;
    const int gid  = lane >> 2;   // 0..7
    const int tg   = lane & 3;    // 0..3

    const int wr  = warp >> 1, wc = warp & 1;   // QK layout
    const int wrp = warp >> 2, wcp = warp & 3;  // PV layout
    const int mA  = wr * 16 + gid;              // QK: A row (and +8)
    const int mP  = wrp * 32 + gid;             // PV: O rows mP, +8, +16, +24
    const int cP  = wcp * 64;                   // PV: col base

    // ---- stage Q tile (tf32-rounded) ----
    for (int i = t; i < 512; i += 256) {
        int mm = i >> 3, d4 = (i & 7) * 4;
        float4 v = *(const float4*)&g_q[((size_t)(b * 4096 + m0 + mm)) * 32 + d4];
        v.x = f2tf_f(v.x); v.y = f2tf_f(v.y); v.z = f2tf_f(v.z); v.w = f2tf_f(v.w);
        *(float4*)&qs[mm * 36 + d4] = v;
    }
    if (t < 64) { Mrow[t] = -INFINITY; lrow[t] = 0.f; }

    float O[2][8][4];   // [m16-frag][c8-frag][reg]
#pragma unroll
    for (int i = 0; i < 2; i++)
#pragma unroll
        for (int j = 0; j < 8; j++)
#pragma unroll
            for (int r = 0; r < 4; r++) O[i][j][r] = 0.f;

    for (int kt = 0; kt < 64; kt++) {
        const int n0 = kt * 64;
        __syncthreads();   // previous iteration readers done with ks/vs

        // ---- stage K tile ----
        for (int i = t; i < 512; i += 256) {
            int nn = i >> 3, d4 = (i & 7) * 4;
            float4 v = *(const float4*)&g_k[((size_t)(b * 4096 + n0 + nn)) * 32 + d4];
            v.x = f2tf_f(v.x); v.y = f2tf_f(v.y); v.z = f2tf_f(v.z); v.w = f2tf_f(v.w);
            *(float4*)&ks[nn * 36 + d4] = v;
        }
        // ---- stage V tile (thread owns channel c = t) ----
        {
            const float4* vp = (const float4*)&g_v[((size_t)(b * 256 + t)) * 4096 + n0];
#pragma unroll
            for (int j4 = 0; j4 < 16; j4++) {
                float4 v = vp[j4];
                vs[(j4 * 4 + 0) * 264 + t] = f2tf_f(v.x);
                vs[(j4 * 4 + 1) * 264 + t] = f2tf_f(v.y);
                vs[(j4 * 4 + 2) * 264 + t] = f2tf_f(v.z);
                vs[(j4 * 4 + 3) * 264 + t] = f2tf_f(v.w);
            }
        }
        __syncthreads();

        // ---- S = Q K^T via tf32 mma: warp computes m16 x n32 ----
        float sD[4][4];
#pragma unroll
        for (int j = 0; j < 4; j++)
#pragma unroll
            for (int r = 0; r < 4; r++) sD[j][r] = 0.f;

#pragma unroll
        for (int kq = 0; kq < 4; kq++) {
            unsigned a[4];
            a[0] = __float_as_uint(qs[mA * 36 + kq * 8 + tg]);
            a[1] = __float_as_uint(qs[(mA + 8) * 36 + kq * 8 + tg]);
            a[2] = __float_as_uint(qs[mA * 36 + kq * 8 + tg + 4]);
            a[3] = __float_as_uint(qs[(mA + 8) * 36 + kq * 8 + tg + 4]);
#pragma unroll
            for (int j = 0; j < 4; j++) {
                int nb = wc * 32 + j * 8 + gid;
                unsigned bf[2];
                bf[0] = __float_as_uint(ks[nb * 36 + kq * 8 + tg]);
                bf[1] = __float_as_uint(ks[nb * 36 + kq * 8 + tg + 4]);
                mma_tf32(sD[j], a, bf);
            }
        }

        // ---- register row-max of this warp's 32 cols ----
        {
            float r0 = -INFINITY, r1 = -INFINITY;
#pragma unroll
            for (int j = 0; j < 4; j++) {
                r0 = fmaxf(r0, fmaxf(sD[j][0], sD[j][1]));
                r1 = fmaxf(r1, fmaxf(sD[j][2], sD[j][3]));
            }
            r0 = fmaxf(r0, __shfl_xor_sync(0xffffffffu, r0, 1));
            r0 = fmaxf(r0, __shfl_xor_sync(0xffffffffu, r0, 2));
            r1 = fmaxf(r1, __shfl_xor_sync(0xffffffffu, r1, 1));
            r1 = fmaxf(r1, __shfl_xor_sync(0xffffffffu, r1, 2));
            if (tg == 0) {
                wmax[wc * 64 + mA]     = r0;
                wmax[wc * 64 + mA + 8] = r1;
            }
        }
        __syncthreads();

        // ---- online-softmax state update ----
        if (t < 64) {
            float oldM = Mrow[t];
            float newM = fmaxf(oldM, fmaxf(wmax[t], wmax[64 + t]));
            fsm[t] = __expf(oldM - newM);
            Mrow[t] = newM;
        }
        __syncthreads();

        // ---- exp in registers -> ps (tf32) + row partial sums ----
        {
            float M0 = Mrow[mA], M1 = Mrow[mA + 8];
            float s0 = 0.f, s1 = 0.f;
#pragma unroll
            for (int j = 0; j < 4; j++) {
                int col = wc * 32 + j * 8 + tg * 2;
                float e00 = f2tf_f(__expf(sD[j][0] - M0));
                float e01 = f2tf_f(__expf(sD[j][1] - M0));
                float e10 = f2tf_f(__expf(sD[j][2] - M1));
                float e11 = f2tf_f(__expf(sD[j][3] - M1));
                s0 += e00 + e01;
                s1 += e10 + e11;
                ps[mA * 68 + col]           = e00;
                ps[mA * 68 + col + 1]       = e01;
                ps[(mA + 8) * 68 + col]     = e10;
                ps[(mA + 8) * 68 + col + 1] = e11;
            }
            s0 += __shfl_xor_sync(0xffffffffu, s0, 1);
            s0 += __shfl_xor_sync(0xffffffffu, s0, 2);
            s1 += __shfl_xor_sync(0xffffffffu, s1, 1);
            s1 += __shfl_xor_sync(0xffffffffu, s1, 2);
            if (tg == 0) {
                psum[wc * 64 + mA]     = s0;
                psum[wc * 64 + mA + 8] = s1;
            }
        }
        __syncthreads();

        if (t < 64)
            lrow[t] = lrow[t] * fsm[t] + psum[t] + psum[64 + t];

        // ---- rescale O accumulators ----
        {
            float f0 = fsm[mP], f1 = fsm[mP + 8], f2 = fsm[mP + 16], f3 = fsm[mP + 24];
#pragma unroll
            for (int j = 0; j < 8; j++) {
                O[0][j][0] *= f0; O[0][j][1] *= f0;
                O[0][j][2] *= f1; O[0][j][3] *= f1;
                O[1][j][0] *= f2; O[1][j][1] *= f2;
                O[1][j][2] *= f3; O[1][j][3] *= f3;
            }
        }

        // ---- O += P V via tf32 mma: warp computes m32 x c64 ----
#pragma unroll
        for (int kn = 0; kn < 8; kn++) {
            unsigned a0[4], a1[4];
            a0[0] = __float_as_uint(ps[mP * 68 + kn * 8 + tg]);
            a0[1] = __float_as_uint(ps[(mP + 8) * 68 + kn * 8 + tg]);
            a0[2] = __float_as_uint(ps[mP * 68 + kn * 8 + tg + 4]);
            a0[3] = __float_as_uint(ps[(mP + 8) * 68 + kn * 8 + tg + 4]);
            a1[0] = __float_as_uint(ps[(mP + 16) * 68 + kn * 8 + tg]);
            a1[1] = __float_as_uint(ps[(mP + 24) * 68 + kn * 8 + tg]);
            a1[2] = __float_as_uint(ps[(mP + 16) * 68 + kn * 8 + tg + 4]);
            a1[3] = __float_as_uint(ps[(mP + 24) * 68 + kn * 8 + tg + 4]);
#pragma unroll
            for (int jc = 0; jc < 8; jc++) {
                unsigned bf[2];
                bf[0] = __float_as_uint(vs[(kn * 8 + tg) * 264 + cP + jc * 8 + gid]);
                bf[1] = __float_as_uint(vs[(kn * 8 + tg + 4) * 264 + cP + jc * 8 + gid]);
                mma_tf32(O[0][jc], a0, bf);
                mma_tf32(O[1][jc], a1, bf);
            }
        }
    }
    __syncthreads();

    // ---- epilogue: scale, transpose via smem [c][m] stride 68, store ----
    const float g = gamma_p[0];
    float scl[4];
    scl[0] = g / lrow[mP];      scl[1] = g / lrow[mP + 8];
    scl[2] = g / lrow[mP + 16]; scl[3] = g / lrow[mP + 24];

    float* smt = ps;   // 256*68 floats, fits in ps..vs region
#pragma unroll
    for (int i2 = 0; i2 < 2; i2++)
#pragma unroll
        for (int jc = 0; jc < 8; jc++) {
            int c = cP + jc * 8 + tg * 2;
            int m = wrp * 32 + i2 * 16 + gid;
            smt[(c)     * 68 + m]     = O[i2][jc][0] * scl[i2 * 2];
            smt[(c + 1) * 68 + m]     = O[i2][jc][1] * scl[i2 * 2];
            smt[(c)     * 68 + m + 8] = O[i2][jc][2] * scl[i2 * 2 + 1];
            smt[(c + 1) * 68 + m + 8] = O[i2][jc][3] * scl[i2 * 2 + 1];
        }
    __syncthreads();

    for (int i4 = t; i4 < 4096; i4 += 256) {
        int c = i4 >> 4, m4 = (i4 & 15) * 4;
        float4 v = *(const float4*)&smt[c * 68 + m4];
        *(float4*)&out[((size_t)(b * 256 + c)) * 4096 + m0 + m4] = v;
    }
}

// =====================================================================
// Kernel 5: out += (1 + lamb * a[b,c]) * x
// =====================================================================
__global__ __launch_bounds__(256) void final_kernel(
    float* __restrict__ out, const float* __restrict__ x,
    const float* __restrict__ lamb)
{
    const int i4  = blockIdx.x * 256 + threadIdx.x;
    const int row = i4 >> 10;
    const float fac = 1.f + lamb[0] * g_a[row];
    float4 xv = ((const float4*)x)[i4];
    float4 ov = ((float4*)out)[i4];
    ov.x = fmaf(fac, xv.x, ov.x);
    ov.y = fmaf(fac, xv.y, ov.y);
    ov.z = fmaf(fac, xv.z, ov.z);
    ov.w = fmaf(fac, xv.w, ov.w);
    ((float4*)out)[i4] = ov;
}

// =====================================================================
extern "C" void kernel_launch(void* const* d_in, const int* in_sizes, int n_in,
                              void* d_out, int out_size)
{
    const float* x     = (const float*)d_in[0];
    const float* Wq    = (const float*)d_in[1];
    const float* bq    = (const float*)d_in[2];
    const float* Wk    = (const float*)d_in[3];
    const float* bk    = (const float*)d_in[4];
    const float* Wv    = (const float*)d_in[5];
    const float* bv    = (const float*)d_in[6];
    const float* gamma = (const float*)d_in[7];
    const float* W1    = (const float*)d_in[8];
    const float* W2    = (const float*)d_in[9];
    const float* lamb  = (const float*)d_in[10];
    float* out = (float*)d_out;

    cudaFuncSetAttribute(attn_kernel,
                         cudaFuncAttributeMaxDynamicSharedMemorySize,
                         SM_TOT * (int)sizeof(float));

    proj_kernel<<<dim3(32, 5, 8), 256>>>(x, Wq, bq, Wk, bk, Wv, bv);
    se_reduce<<<2048, 256>>>(x);
    se_mlp<<<8, 256>>>(W1, W2);
    attn_kernel<<<dim3(64, 8), 256, SM_TOT * sizeof(float)>>>(out, gamma);
    final_kernel<<<8192, 256>>>(out, x, lamb);
}